// round 2
// baseline (speedup 1.0000x reference)
#include <cuda_runtime.h>
#include <cuda_bf16.h>
#include <cstdint>

// Problem constants (fixed shapes from reference setup_inputs)
#define BB   16
#define NN   4096
#define MM   1024
#define C1   256
#define C2   256
#define CIN  512
#define HH   256

// -------- scratch (static device globals; no allocation allowed) -----------
__device__ int   g_i3[BB * NN * 3];                 // 3-NN indices
__device__ float g_w3[BB * NN * 3];                 // 3-NN weights
__device__ float g_f2t[BB * MM * C2];               // feat2 transposed [B][M][C]  (16 MB)
__device__ float g_interp[(size_t)BB * C2 * NN];    // interpolated half of concat (64 MB)
__device__ float g_y1[(size_t)BB * HH * NN];        // layer-1 activations (64 MB)

// ---------------------------------------------------------------------------
// Kernel 1: 3-nearest-neighbor search + normalized inverse-distance weights.
// One thread per query point; xyz2 (+ |q|^2) staged in shared memory.
// ---------------------------------------------------------------------------
__global__ __launch_bounds__(256)
void nn_kernel(const float* __restrict__ xyz1, const float* __restrict__ xyz2)
{
    __shared__ float4 sp[MM];
    const int b = blockIdx.y;
    const float* x2 = xyz2 + (size_t)b * MM * 3;
    for (int i = threadIdx.x; i < MM; i += 256) {
        float x = x2[i * 3 + 0], y = x2[i * 3 + 1], z = x2[i * 3 + 2];
        sp[i] = make_float4(x, y, z, x * x + y * y + z * z);
    }
    __syncthreads();

    const int n = blockIdx.x * 256 + threadIdx.x;
    const float* p = xyz1 + ((size_t)b * NN + n) * 3;
    const float px = p[0], py = p[1], pz = p[2];
    const float s1 = px * px + py * py + pz * pz;

    float d0 = 1e30f, d1 = 1e30f, d2 = 1e30f;
    int   i0 = 0, i1 = 0, i2 = 0;

#pragma unroll 4
    for (int m = 0; m < MM; ++m) {
        const float4 q = sp[m];
        const float dot = px * q.x + py * q.y + pz * q.z;
        const float d = fmaf(-2.0f, dot, s1 + q.w);   // |p|^2 + |q|^2 - 2 p.q
        if (d < d2) {
            if (d < d1) {
                d2 = d1; i2 = i1;
                if (d < d0) { d1 = d0; i1 = i0; d0 = d; i0 = m; }
                else        { d1 = d;  i1 = m; }
            } else { d2 = d; i2 = m; }
        }
    }

    float w0 = 1.0f / (d0 + 1e-8f);
    float w1 = 1.0f / (d1 + 1e-8f);
    float w2 = 1.0f / (d2 + 1e-8f);
    const float ws = w0 + w1 + w2;
    w0 /= ws; w1 /= ws; w2 /= ws;

    const int base = ((b * NN) + n) * 3;
    g_i3[base + 0] = i0; g_i3[base + 1] = i1; g_i3[base + 2] = i2;
    g_w3[base + 0] = w0; g_w3[base + 1] = w1; g_w3[base + 2] = w2;
}

// ---------------------------------------------------------------------------
// Kernel 2: transpose feat2 [B][C][M] -> g_f2t [B][M][C] (coalesced tile xpose)
// ---------------------------------------------------------------------------
__global__ __launch_bounds__(256)
void transpose_kernel(const float* __restrict__ feat2)
{
    __shared__ float tile[32][33];
    const int b  = blockIdx.z;
    const int m0 = blockIdx.x * 32;
    const int c0 = blockIdx.y * 32;
    const float* src = feat2 + (size_t)b * C2 * MM;
    float*       dst = g_f2t + (size_t)b * MM * C2;

#pragma unroll
    for (int i = threadIdx.y; i < 32; i += 8)
        tile[i][threadIdx.x] = src[(size_t)(c0 + i) * MM + m0 + threadIdx.x];
    __syncthreads();
#pragma unroll
    for (int i = threadIdx.y; i < 32; i += 8)
        dst[(size_t)(m0 + i) * C2 + c0 + threadIdx.x] = tile[threadIdx.x][i];
}

// ---------------------------------------------------------------------------
// Kernel 3: weighted 3-row gather -> g_interp [B][C2][N] (channel-major).
// Lanes = consecutive n (coalesced stores); each lane streams 3 contiguous
// 128B row-segments (L1-cached).
// ---------------------------------------------------------------------------
__global__ __launch_bounds__(256)
void interp_kernel()
{
    const int b = blockIdx.y;
    const int n = blockIdx.x * 32 + threadIdx.x;
    const int base = ((b * NN) + n) * 3;
    const int j0 = g_i3[base + 0], j1 = g_i3[base + 1], j2 = g_i3[base + 2];
    const float w0 = g_w3[base + 0], w1 = g_w3[base + 1], w2 = g_w3[base + 2];
    const float* r0 = g_f2t + ((size_t)b * MM + j0) * C2;
    const float* r1 = g_f2t + ((size_t)b * MM + j1) * C2;
    const float* r2 = g_f2t + ((size_t)b * MM + j2) * C2;
    float* out = g_interp + (size_t)b * C2 * NN + n;

    const int c0 = threadIdx.y * 32;
#pragma unroll 8
    for (int c = c0; c < c0 + 32; ++c) {
        out[(size_t)c * NN] = w0 * r0[c] + w1 * r1[c] + w2 * r2[c];
    }
}

// ---------------------------------------------------------------------------
// Kernel 4: fused GEMM + BatchNorm(eval) + ReLU.
//   C[b] = relu( (A @ Bcat[b]) * (gamma/sqrt(1+eps)) + beta )
// A: [256 x K] row-major (weights, shared across batches).
// B operand rows k<S come from B0[b], rows k>=S from B1[b] (implicit concat).
// 128x128 block tile, BK=16, 8x8 per-thread microtile, 256 threads.
// ---------------------------------------------------------------------------
__global__ __launch_bounds__(256, 2)
void gemm_bn_relu(int K, int S,
                  const float* __restrict__ A,
                  const float* __restrict__ B0, const float* __restrict__ B1,
                  float* __restrict__ C,
                  const float* __restrict__ gamma, const float* __restrict__ beta)
{
    const int BM = 128, BN = 128, BK = 16, TM = 8, TN = 8;
    __shared__ float As[BK][BM];
    __shared__ float Bs[BK][BN];

    const int b = blockIdx.z;
    const int rowStart = blockIdx.y * BM;
    const int colStart = blockIdx.x * BN;

    const float* Bb0 = B0 + (size_t)b * S * NN;
    const float* Bb1 = B1 + (size_t)b * (K - S) * NN;
    float*       Cb  = C  + (size_t)b * HH * NN;

    const int tid  = threadIdx.x;
    const int aRow = tid >> 2;          // 0..63
    const int aCol = (tid & 3) * 4;     // 0,4,8,12
    const int bRow = tid >> 5;          // 0..7
    const int bCol = (tid & 31) * 4;    // 0..124

    const int tCol = (tid & 15) * TN;
    const int tRow = (tid >> 4) * TM;

    float acc[TM][TN] = {};
    float regM[TM], regN[TN];

    for (int kt = 0; kt < K; kt += BK) {
        // ---- load A tile (transposed into smem) ----
#pragma unroll
        for (int i = 0; i < 2; ++i) {
            const int r = rowStart + aRow + i * 64;
            const float4 v = *reinterpret_cast<const float4*>(&A[(size_t)r * K + kt + aCol]);
            As[aCol + 0][aRow + i * 64] = v.x;
            As[aCol + 1][aRow + i * 64] = v.y;
            As[aCol + 2][aRow + i * 64] = v.z;
            As[aCol + 3][aRow + i * 64] = v.w;
        }
        // ---- load B tile (dual-source: implicit concat) ----
#pragma unroll
        for (int i = 0; i < 2; ++i) {
            const int kg = kt + bRow + i * 8;
            const float* src = (kg < S) ? (Bb0 + (size_t)kg * NN)
                                        : (Bb1 + (size_t)(kg - S) * NN);
            const float4 v = *reinterpret_cast<const float4*>(&src[colStart + bCol]);
            *reinterpret_cast<float4*>(&Bs[bRow + i * 8][bCol]) = v;
        }
        __syncthreads();

#pragma unroll
        for (int kk = 0; kk < BK; ++kk) {
#pragma unroll
            for (int i = 0; i < TM; i += 4)
                *reinterpret_cast<float4*>(&regM[i]) =
                    *reinterpret_cast<const float4*>(&As[kk][tRow + i]);
#pragma unroll
            for (int j = 0; j < TN; j += 4)
                *reinterpret_cast<float4*>(&regN[j]) =
                    *reinterpret_cast<const float4*>(&Bs[kk][tCol + j]);
#pragma unroll
            for (int i = 0; i < TM; ++i)
#pragma unroll
                for (int j = 0; j < TN; ++j)
                    acc[i][j] = fmaf(regM[i], regN[j], acc[i][j]);
        }
        __syncthreads();
    }

    const float inv = rsqrtf(1.0f + 1e-5f);
#pragma unroll
    for (int i = 0; i < TM; ++i) {
        const int r = rowStart + tRow + i;
        const float sc = gamma[r] * inv;
        const float bi = beta[r];
        float* crow = &Cb[(size_t)r * NN + colStart + tCol];
#pragma unroll
        for (int j = 0; j < TN; j += 4) {
            float4 v;
            v.x = fmaxf(fmaf(acc[i][j + 0], sc, bi), 0.0f);
            v.y = fmaxf(fmaf(acc[i][j + 1], sc, bi), 0.0f);
            v.z = fmaxf(fmaf(acc[i][j + 2], sc, bi), 0.0f);
            v.w = fmaxf(fmaf(acc[i][j + 3], sc, bi), 0.0f);
            *reinterpret_cast<float4*>(&crow[j]) = v;
        }
    }
}

// Tiny helper kernels to obtain the scratch-global addresses on device side
// are unnecessary: device code references the globals directly. For the GEMM
// kernel we still pass pointers; grab them via a device-side publisher.
__device__ float* g_ptrs[3];   // [0]=interp, [1]=y1, [2]=unused
__global__ void publish_ptrs_kernel()
{
    g_ptrs[0] = g_interp;
    g_ptrs[1] = g_y1;
}

// Wrapper GEMM entry points that read scratch pointers from device globals,
// so host code never needs cudaGetSymbolAddress.
__global__ __launch_bounds__(256, 2)
void gemm1_wrapper(const float* __restrict__ A, const float* __restrict__ feat1,
                   const float* __restrict__ gamma, const float* __restrict__ beta);

// Instead of wrappers (which would duplicate the GEMM body), specialize via
// constant selectors: B0/B1/C chosen inside the kernel from an enum.
__global__ __launch_bounds__(256, 2)
void gemm_bn_relu_g(int K, int S, int sel,    // sel=0: B0=g_interp,B1=feat1,C=g_y1 ; sel=1: B0=g_y1,C=out
                    const float* __restrict__ A,
                    const float* __restrict__ Bext,
                    float* __restrict__ Cext,
                    const float* __restrict__ gamma, const float* __restrict__ beta)
{
    const int BM = 128, BN = 128, BK = 16, TM = 8, TN = 8;
    __shared__ float As[BK][BM];
    __shared__ float Bs[BK][BN];

    const int b = blockIdx.z;
    const int rowStart = blockIdx.y * BM;
    const int colStart = blockIdx.x * BN;

    const float* B0 = (sel == 0) ? g_interp : g_y1;
    const float* B1 = Bext;                       // only used when sel==0
    float*       C  = (sel == 0) ? g_y1 : Cext;

    const float* Bb0 = B0 + (size_t)b * S * NN;
    const float* Bb1 = (sel == 0) ? (B1 + (size_t)b * (K - S) * NN) : B0;
    float*       Cb  = C  + (size_t)b * HH * NN;

    const int tid  = threadIdx.x;
    const int aRow = tid >> 2;
    const int aCol = (tid & 3) * 4;
    const int bRow = tid >> 5;
    const int bCol = (tid & 31) * 4;

    const int tCol = (tid & 15) * TN;
    const int tRow = (tid >> 4) * TM;

    float acc[TM][TN] = {};
    float regM[TM], regN[TN];

    for (int kt = 0; kt < K; kt += BK) {
#pragma unroll
        for (int i = 0; i < 2; ++i) {
            const int r = rowStart + aRow + i * 64;
            const float4 v = *reinterpret_cast<const float4*>(&A[(size_t)r * K + kt + aCol]);
            As[aCol + 0][aRow + i * 64] = v.x;
            As[aCol + 1][aRow + i * 64] = v.y;
            As[aCol + 2][aRow + i * 64] = v.z;
            As[aCol + 3][aRow + i * 64] = v.w;
        }
#pragma unroll
        for (int i = 0; i < 2; ++i) {
            const int kg = kt + bRow + i * 8;
            const float* src = (kg < S) ? (Bb0 + (size_t)kg * NN)
                                        : (Bb1 + (size_t)(kg - S) * NN);
            const float4 v = *reinterpret_cast<const float4*>(&src[colStart + bCol]);
            *reinterpret_cast<float4*>(&Bs[bRow + i * 8][bCol]) = v;
        }
        __syncthreads();

#pragma unroll
        for (int kk = 0; kk < BK; ++kk) {
#pragma unroll
            for (int i = 0; i < TM; i += 4)
                *reinterpret_cast<float4*>(&regM[i]) =
                    *reinterpret_cast<const float4*>(&As[kk][tRow + i]);
#pragma unroll
            for (int j = 0; j < TN; j += 4)
                *reinterpret_cast<float4*>(&regN[j]) =
                    *reinterpret_cast<const float4*>(&Bs[kk][tCol + j]);
#pragma unroll
            for (int i = 0; i < TM; ++i)
#pragma unroll
                for (int j = 0; j < TN; ++j)
                    acc[i][j] = fmaf(regM[i], regN[j], acc[i][j]);
        }
        __syncthreads();
    }

    const float inv = rsqrtf(1.0f + 1e-5f);
#pragma unroll
    for (int i = 0; i < TM; ++i) {
        const int r = rowStart + tRow + i;
        const float sc = gamma[r] * inv;
        const float bi = beta[r];
        float* crow = &Cb[(size_t)r * NN + colStart + tCol];
#pragma unroll
        for (int j = 0; j < TN; j += 4) {
            float4 v;
            v.x = fmaxf(fmaf(acc[i][j + 0], sc, bi), 0.0f);
            v.y = fmaxf(fmaf(acc[i][j + 1], sc, bi), 0.0f);
            v.z = fmaxf(fmaf(acc[i][j + 2], sc, bi), 0.0f);
            v.w = fmaxf(fmaf(acc[i][j + 3], sc, bi), 0.0f);
            *reinterpret_cast<float4*>(&crow[j]) = v;
        }
    }
}

// ---------------------------------------------------------------------------
extern "C" void kernel_launch(void* const* d_in, const int* in_sizes, int n_in,
                              void* d_out, int out_size)
{
    const float* xyz1   = (const float*)d_in[0];
    const float* xyz2   = (const float*)d_in[1];
    const float* feat1  = (const float*)d_in[2];
    const float* feat2  = (const float*)d_in[3];
    const float* w1     = (const float*)d_in[4];
    const float* gamma1 = (const float*)d_in[5];
    const float* beta1  = (const float*)d_in[6];
    const float* w2     = (const float*)d_in[7];
    const float* gamma2 = (const float*)d_in[8];
    const float* beta2  = (const float*)d_in[9];
    float* out = (float*)d_out;

    // 1) 3-NN + weights
    nn_kernel<<<dim3(NN / 256, BB), 256>>>(xyz1, xyz2);
    // 2) transpose feat2 to point-major
    transpose_kernel<<<dim3(MM / 32, C2 / 32, BB), dim3(32, 8)>>>(feat2);
    // 3) weighted gather -> g_interp [B][C2][N]
    interp_kernel<<<dim3(NN / 32, BB), dim3(32, 8)>>>();
    // 4) layer 1: [256x512] @ concat(g_interp, feat1) + BN + ReLU -> g_y1
    gemm_bn_relu_g<<<dim3(NN / 128, HH / 128, BB), 256>>>(
        CIN, C2, 0, w1, feat1, nullptr, gamma1, beta1);
    // 5) layer 2: [256x256] @ g_y1 + BN + ReLU -> out
    gemm_bn_relu_g<<<dim3(NN / 128, HH / 128, BB), 256>>>(
        HH, HH, 1, w2, nullptr, out, gamma2, beta2);
}

// round 5
// speedup vs baseline: 1.8432x; 1.8432x over previous
#include <cuda_runtime.h>
#include <cuda_bf16.h>
#include <cstdint>

// Problem constants (fixed shapes from reference setup_inputs)
#define BB   16
#define NN   4096
#define MM   1024
#define C1   256
#define C2   256
#define CIN  512
#define HH   256

// ---------------- scratch (static device globals) --------------------------
__device__ int   g_i3[BB * NN * 3];
__device__ float g_w3[BB * NN * 3];
__device__ float g_f2t[BB * MM * C2];                    // feat2 point-major fp32
__device__ __align__(16) float g_x [(size_t)BB * NN * CIN];  // concat input, point-major, tf32-rounded
__device__ __align__(16) float g_y1[(size_t)BB * NN * HH];   // layer1 out, point-major, tf32-rounded

// ---------------- helpers ---------------------------------------------------
__device__ __forceinline__ float tf32r(float x) {
    uint32_t u;
    asm("cvt.rna.tf32.f32 %0, %1;" : "=r"(u) : "f"(x));
    return __uint_as_float(u);
}

__device__ __forceinline__ void mma_tf32(float* d, const uint32_t* a, const uint32_t* b) {
    asm volatile(
        "mma.sync.aligned.m16n8k8.row.col.f32.tf32.tf32.f32 "
        "{%0,%1,%2,%3}, {%4,%5,%6,%7}, {%8,%9}, {%0,%1,%2,%3};"
        : "+f"(d[0]), "+f"(d[1]), "+f"(d[2]), "+f"(d[3])
        : "r"(a[0]), "r"(a[1]), "r"(a[2]), "r"(a[3]), "r"(b[0]), "r"(b[1]));
}

// ---------------------------------------------------------------------------
// Kernel 1: 3-NN search + normalized inverse-distance weights.
// ---------------------------------------------------------------------------
__global__ __launch_bounds__(256)
void nn_kernel(const float* __restrict__ xyz1, const float* __restrict__ xyz2)
{
    __shared__ float4 sp[MM];
    const int b = blockIdx.y;
    const float* x2 = xyz2 + (size_t)b * MM * 3;
    for (int i = threadIdx.x; i < MM; i += 256) {
        float x = x2[i * 3 + 0], y = x2[i * 3 + 1], z = x2[i * 3 + 2];
        sp[i] = make_float4(x, y, z, x * x + y * y + z * z);
    }
    __syncthreads();

    const int n = blockIdx.x * 256 + threadIdx.x;
    const float* p = xyz1 + ((size_t)b * NN + n) * 3;
    const float px = p[0], py = p[1], pz = p[2];
    const float s1 = px * px + py * py + pz * pz;

    float d0 = 1e30f, d1 = 1e30f, d2 = 1e30f;
    int   i0 = 0, i1 = 0, i2 = 0;
#pragma unroll 4
    for (int m = 0; m < MM; ++m) {
        const float4 q = sp[m];
        const float dot = px * q.x + py * q.y + pz * q.z;
        const float d = fmaf(-2.0f, dot, s1 + q.w);
        if (d < d2) {
            if (d < d1) {
                d2 = d1; i2 = i1;
                if (d < d0) { d1 = d0; i1 = i0; d0 = d; i0 = m; }
                else        { d1 = d;  i1 = m; }
            } else { d2 = d; i2 = m; }
        }
    }
    float w0 = 1.0f / (d0 + 1e-8f);
    float w1 = 1.0f / (d1 + 1e-8f);
    float w2 = 1.0f / (d2 + 1e-8f);
    const float ws = w0 + w1 + w2;
    w0 /= ws; w1 /= ws; w2 /= ws;

    const int base = ((b * NN) + n) * 3;
    g_i3[base + 0] = i0; g_i3[base + 1] = i1; g_i3[base + 2] = i2;
    g_w3[base + 0] = w0; g_w3[base + 1] = w1; g_w3[base + 2] = w2;
}

// ---------------------------------------------------------------------------
// Kernel 2: transpose feat2 [B][C][M] -> g_f2t [B][M][C] fp32
// ---------------------------------------------------------------------------
__global__ __launch_bounds__(256)
void f2t_kernel(const float* __restrict__ feat2)
{
    __shared__ float tile[32][33];
    const int b  = blockIdx.z;
    const int m0 = blockIdx.x * 32;
    const int c0 = blockIdx.y * 32;
    const float* src = feat2 + (size_t)b * C2 * MM;
    float*       dst = g_f2t + (size_t)b * MM * C2;
#pragma unroll
    for (int i = threadIdx.y; i < 32; i += 8)
        tile[i][threadIdx.x] = src[(size_t)(c0 + i) * MM + m0 + threadIdx.x];
    __syncthreads();
#pragma unroll
    for (int i = threadIdx.y; i < 32; i += 8)
        dst[(size_t)(m0 + i) * C2 + c0 + threadIdx.x] = tile[threadIdx.x][i];
}

// ---------------------------------------------------------------------------
// Kernel 3: 3-point weighted gather -> g_x channels [0,256), tf32-rounded.
// One warp per point; coalesced loads (contig rows) and stores.
// ---------------------------------------------------------------------------
__global__ __launch_bounds__(256)
void interp_x_kernel()
{
    const int b    = blockIdx.y;
    const int warp = threadIdx.x >> 5;
    const int lane = threadIdx.x & 31;
    const int n    = blockIdx.x * 8 + warp;

    const int base = ((b * NN) + n) * 3;
    const int j0 = g_i3[base + 0], j1 = g_i3[base + 1], j2 = g_i3[base + 2];
    const float w0 = g_w3[base + 0], w1 = g_w3[base + 1], w2 = g_w3[base + 2];

    const float4* r0 = (const float4*)(g_f2t + ((size_t)b * MM + j0) * C2);
    const float4* r1 = (const float4*)(g_f2t + ((size_t)b * MM + j1) * C2);
    const float4* r2 = (const float4*)(g_f2t + ((size_t)b * MM + j2) * C2);

    float4* ox = (float4*)(g_x + ((size_t)b * NN + n) * CIN);

#pragma unroll
    for (int i = lane; i < 64; i += 32) {       // 64 float4 = 256 channels
        const float4 a = r0[i], c = r1[i], d = r2[i];
        float4 v;
        v.x = tf32r(w0 * a.x + w1 * c.x + w2 * d.x);
        v.y = tf32r(w0 * a.y + w1 * c.y + w2 * d.y);
        v.z = tf32r(w0 * a.z + w1 * c.z + w2 * d.z);
        v.w = tf32r(w0 * a.w + w1 * c.w + w2 * d.w);
        ox[i] = v;
    }
}

// ---------------------------------------------------------------------------
// Kernel 4: feat1 [B][C][N] -> g_x channels [256,512), tf32-rounded.
// ---------------------------------------------------------------------------
__global__ __launch_bounds__(256)
void feat1_x_kernel(const float* __restrict__ feat1)
{
    __shared__ float tile[32][33];
    const int b  = blockIdx.z;
    const int n0 = blockIdx.x * 32;
    const int c0 = blockIdx.y * 32;
    const float* src = feat1 + (size_t)b * C1 * NN;
#pragma unroll
    for (int i = threadIdx.y; i < 32; i += 8)
        tile[i][threadIdx.x] = src[(size_t)(c0 + i) * NN + n0 + threadIdx.x];
    __syncthreads();
#pragma unroll
    for (int i = threadIdx.y; i < 32; i += 8) {
        const int n = n0 + i;
        const int c = c0 + threadIdx.x;
        g_x[((size_t)b * NN + n) * CIN + C2 + c] = tf32r(tile[threadIdx.x][i]);
    }
}

// ---------------------------------------------------------------------------
// Kernel 5: tf32 mma.sync GEMM + BN + ReLU.
//   C[b](128x128 tile) = relu( W(128xK) @ X[b](Kx128) * scale + bias )
// 8 warps, warp tile 64x32 via m16n8k8 tf32 (4x4 frags), BK=32, double buffer.
// Smem tiles stored in fragment order (conflict-free LDS.128/LDS.64).
// MODE 0: X=g_x,  Y=g_y1 point-major tf32-rounded.
// MODE 1: X=g_y1, Y=outp channel-major fp32.
// ---------------------------------------------------------------------------
#define CS_STRIDE 132
#define DYN_BYTES (128 * CS_STRIDE * 4)   // 67584 >= mainloop's 65536

template <int K, int MODE>
__global__ __launch_bounds__(256)
void gemm_mma(const float* __restrict__ W,
              float* __restrict__ outp,
              const float* __restrict__ gamma, const float* __restrict__ beta)
{
    extern __shared__ float smem[];
    float* sA[2] = { smem,          smem + 8192  };   // each 4096 floats
    float* sB[2] = { smem + 4096,   smem + 12288 };

    const float* X = (MODE == 0) ? g_x : g_y1;
    float*       Y = (MODE == 0) ? g_y1 : outp;

    const int b        = blockIdx.z;
    const int rowStart = blockIdx.y * 128;
    const int colStart = blockIdx.x * 128;
    const int tid  = threadIdx.x;
    const int wid  = tid >> 5;
    const int lane = tid & 31;
    const int gq   = lane >> 2;       // groupID 0..7
    const int tq   = lane & 3;        // thread-in-group 0..3
    const int wm   = wid & 1;         // warp m-tile (64 rows)
    const int wn   = wid >> 1;        // warp n-tile (32 cols)

    const float* Xb = X + ((size_t)b * NN + colStart) * K;

    float acc[4][4][4];
#pragma unroll
    for (int i = 0; i < 4; ++i)
#pragma unroll
        for (int j = 0; j < 4; ++j)
#pragma unroll
            for (int r = 0; r < 4; ++r) acc[i][j][r] = 0.0f;

    float rA[16], rB[16];

    // per-thread loader geometry (constant across chunks)
    int a_base[4], b_base[4], g_row[4], g_c0[4];
#pragma unroll
    for (int it = 0; it < 4; ++it) {
        const int idx = tid + it * 256;
        const int r   = idx >> 3;             // 0..127
        const int c0  = (idx & 7) * 4;        // 0..28
        g_row[it] = r; g_c0[it] = c0;
        const int m = r >> 4, rr = r & 15, gg = rr & 7, reg0 = rr >> 3;
        const int kstep = c0 >> 3, reg1 = (c0 >> 2) & 1;
        a_base[it] = (((m * 4 + kstep) * 32 + gg * 4) * 4) + reg0 + 2 * reg1;
        const int nf = r >> 3, gid = r & 7;
        b_base[it] = (((nf * 4 + kstep) * 32 + gid * 4) * 2) + reg1;
    }

    const int NCH = K / 32;

    // prologue: chunk 0 -> buf 0
#pragma unroll
    for (int it = 0; it < 4; ++it) {
        const float4 va = *(const float4*)(W  + (size_t)(rowStart + g_row[it]) * K + g_c0[it]);
        const float4 vb = *(const float4*)(Xb + (size_t)g_row[it] * K + g_c0[it]);
        float* A0 = sA[0]; float* B0 = sB[0];
        A0[a_base[it] + 0]  = tf32r(va.x);
        A0[a_base[it] + 4]  = tf32r(va.y);
        A0[a_base[it] + 8]  = tf32r(va.z);
        A0[a_base[it] + 12] = tf32r(va.w);
        B0[b_base[it] + 0] = vb.x;
        B0[b_base[it] + 2] = vb.y;
        B0[b_base[it] + 4] = vb.z;
        B0[b_base[it] + 6] = vb.w;
    }
    __syncthreads();

    for (int ch = 0; ch < NCH; ++ch) {
        const int buf = ch & 1;
        const bool more = (ch + 1 < NCH);
        if (more) {
            const int kt = (ch + 1) * 32;
#pragma unroll
            for (int it = 0; it < 4; ++it) {
                const float4 va = *(const float4*)(W  + (size_t)(rowStart + g_row[it]) * K + kt + g_c0[it]);
                rA[it * 4 + 0] = tf32r(va.x);
                rA[it * 4 + 1] = tf32r(va.y);
                rA[it * 4 + 2] = tf32r(va.z);
                rA[it * 4 + 3] = tf32r(va.w);
                const float4 vb = *(const float4*)(Xb + (size_t)g_row[it] * K + kt + g_c0[it]);
                rB[it * 4 + 0] = vb.x;
                rB[it * 4 + 1] = vb.y;
                rB[it * 4 + 2] = vb.z;
                rB[it * 4 + 3] = vb.w;
            }
        }

        const float* cA = sA[buf];
        const float* cB = sB[buf];
#pragma unroll
        for (int ks = 0; ks < 4; ++ks) {
            uint32_t af[4][4];
            uint32_t bf[4][2];
#pragma unroll
            for (int i = 0; i < 4; ++i) {
                const uint4 v = *(const uint4*)(cA + (((wm * 4 + i) * 4 + ks) * 32 + lane) * 4);
                af[i][0] = v.x; af[i][1] = v.y; af[i][2] = v.z; af[i][3] = v.w;
            }
#pragma unroll
            for (int j = 0; j < 4; ++j) {
                const uint2 v = *(const uint2*)(cB + (((wn * 4 + j) * 4 + ks) * 32 + lane) * 2);
                bf[j][0] = v.x; bf[j][1] = v.y;
            }
#pragma unroll
            for (int i = 0; i < 4; ++i)
#pragma unroll
                for (int j = 0; j < 4; ++j)
                    mma_tf32(acc[i][j], af[i], bf[j]);
        }

        if (more) {
            float* nA = sA[buf ^ 1];
            float* nB = sB[buf ^ 1];
#pragma unroll
            for (int it = 0; it < 4; ++it) {
                nA[a_base[it] + 0]  = rA[it * 4 + 0];
                nA[a_base[it] + 4]  = rA[it * 4 + 1];
                nA[a_base[it] + 8]  = rA[it * 4 + 2];
                nA[a_base[it] + 12] = rA[it * 4 + 3];
                nB[b_base[it] + 0] = rB[it * 4 + 0];
                nB[b_base[it] + 2] = rB[it * 4 + 1];
                nB[b_base[it] + 4] = rB[it * 4 + 2];
                nB[b_base[it] + 6] = rB[it * 4 + 3];
            }
        }
        __syncthreads();
    }

    // ---- epilogue: BN + ReLU, stage through smem for coalesced stores ----
    const float inv = rsqrtf(1.0f + 1e-5f);
    float* Cs = smem;                          // reuse (all compute done)

#pragma unroll
    for (int i = 0; i < 4; ++i) {
        const int h0 = wm * 64 + i * 16 + gq;  // rows for c0,c1
        const int h1 = h0 + 8;                 // rows for c2,c3
        const float sc0 = gamma[rowStart + h0] * inv, bi0 = beta[rowStart + h0];
        const float sc1 = gamma[rowStart + h1] * inv, bi1 = beta[rowStart + h1];
#pragma unroll
        for (int j = 0; j < 4; ++j) {
            const int n0 = wn * 32 + j * 8 + 2 * tq;
            float v0 = fmaxf(fmaf(acc[i][j][0], sc0, bi0), 0.0f);
            float v1 = fmaxf(fmaf(acc[i][j][1], sc0, bi0), 0.0f);
            float v2 = fmaxf(fmaf(acc[i][j][2], sc1, bi1), 0.0f);
            float v3 = fmaxf(fmaf(acc[i][j][3], sc1, bi1), 0.0f);
            if (MODE == 0) { v0 = tf32r(v0); v1 = tf32r(v1); v2 = tf32r(v2); v3 = tf32r(v3); }
            if (MODE == 0) {
                // Cs[n][h]
                Cs[(n0 + 0) * CS_STRIDE + h0] = v0;
                Cs[(n0 + 1) * CS_STRIDE + h0] = v1;
                Cs[(n0 + 0) * CS_STRIDE + h1] = v2;
                Cs[(n0 + 1) * CS_STRIDE + h1] = v3;
            } else {
                // Cs[h][n]
                Cs[h0 * CS_STRIDE + n0 + 0] = v0;
                Cs[h0 * CS_STRIDE + n0 + 1] = v1;
                Cs[h1 * CS_STRIDE + n0 + 0] = v2;
                Cs[h1 * CS_STRIDE + n0 + 1] = v3;
            }
        }
    }
    __syncthreads();

#pragma unroll
    for (int it = 0; it < 16; ++it) {
        const int idx = tid + it * 256;        // 0..4095 float4s
        const int r = idx >> 5;                // staged row 0..127
        const int f = idx & 31;                // float4 within row
        const float4 v = *(const float4*)(Cs + r * CS_STRIDE + f * 4);
        if (MODE == 0) {
            // Y = g_y1 [B][N][HH]: row r = point, cols = channels
            *(float4*)(Y + ((size_t)b * NN + colStart + r) * HH + rowStart + f * 4) = v;
        } else {
            // Y = out [B][HH][NN]: row r = channel, cols = points
            *(float4*)(Y + ((size_t)b * HH + rowStart + r) * NN + colStart + f * 4) = v;
        }
    }
}

// ---------------------------------------------------------------------------
extern "C" void kernel_launch(void* const* d_in, const int* in_sizes, int n_in,
                              void* d_out, int out_size)
{
    const float* xyz1   = (const float*)d_in[0];
    const float* xyz2   = (const float*)d_in[1];
    const float* feat1  = (const float*)d_in[2];
    const float* feat2  = (const float*)d_in[3];
    const float* w1     = (const float*)d_in[4];
    const float* gamma1 = (const float*)d_in[5];
    const float* beta1  = (const float*)d_in[6];
    const float* w2     = (const float*)d_in[7];
    const float* gamma2 = (const float*)d_in[8];
    const float* beta2  = (const float*)d_in[9];
    float* out = (float*)d_out;

    cudaFuncSetAttribute(gemm_mma<CIN, 0>, cudaFuncAttributeMaxDynamicSharedMemorySize, DYN_BYTES);
    cudaFuncSetAttribute(gemm_mma<HH, 1>,  cudaFuncAttributeMaxDynamicSharedMemorySize, DYN_BYTES);

    // 1) 3-NN + weights
    nn_kernel<<<dim3(NN / 256, BB), 256>>>(xyz1, xyz2);
    // 2) feat2 -> point-major fp32
    f2t_kernel<<<dim3(MM / 32, C2 / 32, BB), dim3(32, 8)>>>(feat2);
    // 3) gather -> g_x channels [0,256)
    interp_x_kernel<<<dim3(NN / 8, BB), 256>>>();
    // 4) feat1 -> g_x channels [256,512)
    feat1_x_kernel<<<dim3(NN / 32, C1 / 32, BB), dim3(32, 8)>>>(feat1);
    // 5) layer 1: tf32 GEMM (K=512) + BN + ReLU -> g_y1 (point-major)
    gemm_mma<CIN, 0><<<dim3(NN / 128, HH / 128, BB), 256, DYN_BYTES>>>(w1, nullptr, gamma1, beta1);
    // 6) layer 2: tf32 GEMM (K=256) + BN + ReLU -> out (channel-major)
    gemm_mma<HH, 1><<<dim3(NN / 128, HH / 128, BB), 256, DYN_BYTES>>>(w2, out, gamma2, beta2);
}

// round 6
// speedup vs baseline: 1.8443x; 1.0006x over previous
#include <cuda_runtime.h>
#include <cuda_bf16.h>
#include <cstdint>

// Problem constants (fixed shapes from reference setup_inputs)
#define BB   16
#define NN   4096
#define MM   1024
#define C1   256
#define C2   256
#define CIN  512
#define HH   256

// ---------------- scratch (static device globals) --------------------------
__device__ int   g_i3[BB * NN * 3];
__device__ float g_w3[BB * NN * 3];
__device__ float g_f2t[BB * MM * C2];                    // feat2 point-major fp32
__device__ __align__(16) float g_x [(size_t)BB * NN * CIN];  // concat input, point-major, tf32-rounded
__device__ __align__(16) float g_y1[(size_t)BB * NN * HH];   // layer1 out, point-major, tf32-rounded

// ---------------- helpers ---------------------------------------------------
__device__ __forceinline__ float tf32r(float x) {
    uint32_t u;
    asm("cvt.rna.tf32.f32 %0, %1;" : "=r"(u) : "f"(x));
    return __uint_as_float(u);
}

__device__ __forceinline__ void mma_tf32(float* d, const uint32_t* a, const uint32_t* b) {
    asm volatile(
        "mma.sync.aligned.m16n8k8.row.col.f32.tf32.tf32.f32 "
        "{%0,%1,%2,%3}, {%4,%5,%6,%7}, {%8,%9}, {%0,%1,%2,%3};"
        : "+f"(d[0]), "+f"(d[1]), "+f"(d[2]), "+f"(d[3])
        : "r"(a[0]), "r"(a[1]), "r"(a[2]), "r"(a[3]), "r"(b[0]), "r"(b[1]));
}

// ---------------------------------------------------------------------------
// Kernel 1: 3-NN search + normalized inverse-distance weights.
// ---------------------------------------------------------------------------
__global__ __launch_bounds__(256)
void nn_kernel(const float* __restrict__ xyz1, const float* __restrict__ xyz2)
{
    __shared__ float4 sp[MM];
    const int b = blockIdx.y;
    const float* x2 = xyz2 + (size_t)b * MM * 3;
    for (int i = threadIdx.x; i < MM; i += 256) {
        float x = x2[i * 3 + 0], y = x2[i * 3 + 1], z = x2[i * 3 + 2];
        sp[i] = make_float4(x, y, z, x * x + y * y + z * z);
    }
    __syncthreads();

    const int n = blockIdx.x * 256 + threadIdx.x;
    const float* p = xyz1 + ((size_t)b * NN + n) * 3;
    const float px = p[0], py = p[1], pz = p[2];
    const float s1 = px * px + py * py + pz * pz;

    float d0 = 1e30f, d1 = 1e30f, d2 = 1e30f;
    int   i0 = 0, i1 = 0, i2 = 0;
#pragma unroll 4
    for (int m = 0; m < MM; ++m) {
        const float4 q = sp[m];
        const float dot = px * q.x + py * q.y + pz * q.z;
        const float d = fmaf(-2.0f, dot, s1 + q.w);
        if (d < d2) {
            if (d < d1) {
                d2 = d1; i2 = i1;
                if (d < d0) { d1 = d0; i1 = i0; d0 = d; i0 = m; }
                else        { d1 = d;  i1 = m; }
            } else { d2 = d; i2 = m; }
        }
    }
    float w0 = 1.0f / (d0 + 1e-8f);
    float w1 = 1.0f / (d1 + 1e-8f);
    float w2 = 1.0f / (d2 + 1e-8f);
    const float ws = w0 + w1 + w2;
    w0 /= ws; w1 /= ws; w2 /= ws;

    const int base = ((b * NN) + n) * 3;
    g_i3[base + 0] = i0; g_i3[base + 1] = i1; g_i3[base + 2] = i2;
    g_w3[base + 0] = w0; g_w3[base + 1] = w1; g_w3[base + 2] = w2;
}

// ---------------------------------------------------------------------------
// Kernel 2: transpose feat2 [B][C][M] -> g_f2t [B][M][C] fp32
// ---------------------------------------------------------------------------
__global__ __launch_bounds__(256)
void f2t_kernel(const float* __restrict__ feat2)
{
    __shared__ float tile[32][33];
    const int b  = blockIdx.z;
    const int m0 = blockIdx.x * 32;
    const int c0 = blockIdx.y * 32;
    const float* src = feat2 + (size_t)b * C2 * MM;
    float*       dst = g_f2t + (size_t)b * MM * C2;
#pragma unroll
    for (int i = threadIdx.y; i < 32; i += 8)
        tile[i][threadIdx.x] = src[(size_t)(c0 + i) * MM + m0 + threadIdx.x];
    __syncthreads();
#pragma unroll
    for (int i = threadIdx.y; i < 32; i += 8)
        dst[(size_t)(m0 + i) * C2 + c0 + threadIdx.x] = tile[threadIdx.x][i];
}

// ---------------------------------------------------------------------------
// Kernel 3: 3-point weighted gather -> g_x channels [0,256), tf32-rounded.
// One warp per point; coalesced loads (contig rows) and stores.
// ---------------------------------------------------------------------------
__global__ __launch_bounds__(256)
void interp_x_kernel()
{
    const int b    = blockIdx.y;
    const int warp = threadIdx.x >> 5;
    const int lane = threadIdx.x & 31;
    const int n    = blockIdx.x * 8 + warp;

    const int base = ((b * NN) + n) * 3;
    const int j0 = g_i3[base + 0], j1 = g_i3[base + 1], j2 = g_i3[base + 2];
    const float w0 = g_w3[base + 0], w1 = g_w3[base + 1], w2 = g_w3[base + 2];

    const float4* r0 = (const float4*)(g_f2t + ((size_t)b * MM + j0) * C2);
    const float4* r1 = (const float4*)(g_f2t + ((size_t)b * MM + j1) * C2);
    const float4* r2 = (const float4*)(g_f2t + ((size_t)b * MM + j2) * C2);

    float4* ox = (float4*)(g_x + ((size_t)b * NN + n) * CIN);

#pragma unroll
    for (int i = lane; i < 64; i += 32) {       // 64 float4 = 256 channels
        const float4 a = r0[i], c = r1[i], d = r2[i];
        float4 v;
        v.x = tf32r(w0 * a.x + w1 * c.x + w2 * d.x);
        v.y = tf32r(w0 * a.y + w1 * c.y + w2 * d.y);
        v.z = tf32r(w0 * a.z + w1 * c.z + w2 * d.z);
        v.w = tf32r(w0 * a.w + w1 * c.w + w2 * d.w);
        ox[i] = v;
    }
}

// ---------------------------------------------------------------------------
// Kernel 4: feat1 [B][C][N] -> g_x channels [256,512), tf32-rounded.
// ---------------------------------------------------------------------------
__global__ __launch_bounds__(256)
void feat1_x_kernel(const float* __restrict__ feat1)
{
    __shared__ float tile[32][33];
    const int b  = blockIdx.z;
    const int n0 = blockIdx.x * 32;
    const int c0 = blockIdx.y * 32;
    const float* src = feat1 + (size_t)b * C1 * NN;
#pragma unroll
    for (int i = threadIdx.y; i < 32; i += 8)
        tile[i][threadIdx.x] = src[(size_t)(c0 + i) * NN + n0 + threadIdx.x];
    __syncthreads();
#pragma unroll
    for (int i = threadIdx.y; i < 32; i += 8) {
        const int n = n0 + i;
        const int c = c0 + threadIdx.x;
        g_x[((size_t)b * NN + n) * CIN + C2 + c] = tf32r(tile[threadIdx.x][i]);
    }
}

// ---------------------------------------------------------------------------
// Kernel 5: tf32 mma.sync GEMM + BN + ReLU.
//   C[b](128x128 tile) = relu( W(128xK) @ X[b](Kx128) * scale + bias )
// 8 warps, warp tile 64x32 via m16n8k8 tf32 (4x4 frags), BK=32, double buffer.
// Smem tiles stored in fragment order (conflict-free LDS.128/LDS.64).
// MODE 0: X=g_x,  Y=g_y1 point-major tf32-rounded.
// MODE 1: X=g_y1, Y=outp channel-major fp32.
// ---------------------------------------------------------------------------
#define CS_STRIDE 132
#define DYN_BYTES (128 * CS_STRIDE * 4)   // 67584 >= mainloop's 65536

template <int K, int MODE>
__global__ __launch_bounds__(256)
void gemm_mma(const float* __restrict__ W,
              float* __restrict__ outp,
              const float* __restrict__ gamma, const float* __restrict__ beta)
{
    extern __shared__ float smem[];
    float* sA[2] = { smem,          smem + 8192  };   // each 4096 floats
    float* sB[2] = { smem + 4096,   smem + 12288 };

    const float* X = (MODE == 0) ? g_x : g_y1;
    float*       Y = (MODE == 0) ? g_y1 : outp;

    const int b        = blockIdx.z;
    const int rowStart = blockIdx.y * 128;
    const int colStart = blockIdx.x * 128;
    const int tid  = threadIdx.x;
    const int wid  = tid >> 5;
    const int lane = tid & 31;
    const int gq   = lane >> 2;       // groupID 0..7
    const int tq   = lane & 3;        // thread-in-group 0..3
    const int wm   = wid & 1;         // warp m-tile (64 rows)
    const int wn   = wid >> 1;        // warp n-tile (32 cols)

    const float* Xb = X + ((size_t)b * NN + colStart) * K;

    float acc[4][4][4];
#pragma unroll
    for (int i = 0; i < 4; ++i)
#pragma unroll
        for (int j = 0; j < 4; ++j)
#pragma unroll
            for (int r = 0; r < 4; ++r) acc[i][j][r] = 0.0f;

    float rA[16], rB[16];

    // per-thread loader geometry (constant across chunks)
    int a_base[4], b_base[4], g_row[4], g_c0[4];
#pragma unroll
    for (int it = 0; it < 4; ++it) {
        const int idx = tid + it * 256;
        const int r   = idx >> 3;             // 0..127
        const int c0  = (idx & 7) * 4;        // 0..28
        g_row[it] = r; g_c0[it] = c0;
        const int m = r >> 4, rr = r & 15, gg = rr & 7, reg0 = rr >> 3;
        const int kstep = c0 >> 3, reg1 = (c0 >> 2) & 1;
        a_base[it] = (((m * 4 + kstep) * 32 + gg * 4) * 4) + reg0 + 2 * reg1;
        const int nf = r >> 3, gid = r & 7;
        b_base[it] = (((nf * 4 + kstep) * 32 + gid * 4) * 2) + reg1;
    }

    const int NCH = K / 32;

    // prologue: chunk 0 -> buf 0
#pragma unroll
    for (int it = 0; it < 4; ++it) {
        const float4 va = *(const float4*)(W  + (size_t)(rowStart + g_row[it]) * K + g_c0[it]);
        const float4 vb = *(const float4*)(Xb + (size_t)g_row[it] * K + g_c0[it]);
        float* A0 = sA[0]; float* B0 = sB[0];
        A0[a_base[it] + 0]  = tf32r(va.x);
        A0[a_base[it] + 4]  = tf32r(va.y);
        A0[a_base[it] + 8]  = tf32r(va.z);
        A0[a_base[it] + 12] = tf32r(va.w);
        B0[b_base[it] + 0] = vb.x;
        B0[b_base[it] + 2] = vb.y;
        B0[b_base[it] + 4] = vb.z;
        B0[b_base[it] + 6] = vb.w;
    }
    __syncthreads();

    for (int ch = 0; ch < NCH; ++ch) {
        const int buf = ch & 1;
        const bool more = (ch + 1 < NCH);
        if (more) {
            const int kt = (ch + 1) * 32;
#pragma unroll
            for (int it = 0; it < 4; ++it) {
                const float4 va = *(const float4*)(W  + (size_t)(rowStart + g_row[it]) * K + kt + g_c0[it]);
                rA[it * 4 + 0] = tf32r(va.x);
                rA[it * 4 + 1] = tf32r(va.y);
                rA[it * 4 + 2] = tf32r(va.z);
                rA[it * 4 + 3] = tf32r(va.w);
                const float4 vb = *(const float4*)(Xb + (size_t)g_row[it] * K + kt + g_c0[it]);
                rB[it * 4 + 0] = vb.x;
                rB[it * 4 + 1] = vb.y;
                rB[it * 4 + 2] = vb.z;
                rB[it * 4 + 3] = vb.w;
            }
        }

        const float* cA = sA[buf];
        const float* cB = sB[buf];
#pragma unroll
        for (int ks = 0; ks < 4; ++ks) {
            uint32_t af[4][4];
            uint32_t bf[4][2];
#pragma unroll
            for (int i = 0; i < 4; ++i) {
                const uint4 v = *(const uint4*)(cA + (((wm * 4 + i) * 4 + ks) * 32 + lane) * 4);
                af[i][0] = v.x; af[i][1] = v.y; af[i][2] = v.z; af[i][3] = v.w;
            }
#pragma unroll
            for (int j = 0; j < 4; ++j) {
                const uint2 v = *(const uint2*)(cB + (((wn * 4 + j) * 4 + ks) * 32 + lane) * 2);
                bf[j][0] = v.x; bf[j][1] = v.y;
            }
#pragma unroll
            for (int i = 0; i < 4; ++i)
#pragma unroll
                for (int j = 0; j < 4; ++j)
                    mma_tf32(acc[i][j], af[i], bf[j]);
        }

        if (more) {
            float* nA = sA[buf ^ 1];
            float* nB = sB[buf ^ 1];
#pragma unroll
            for (int it = 0; it < 4; ++it) {
                nA[a_base[it] + 0]  = rA[it * 4 + 0];
                nA[a_base[it] + 4]  = rA[it * 4 + 1];
                nA[a_base[it] + 8]  = rA[it * 4 + 2];
                nA[a_base[it] + 12] = rA[it * 4 + 3];
                nB[b_base[it] + 0] = rB[it * 4 + 0];
                nB[b_base[it] + 2] = rB[it * 4 + 1];
                nB[b_base[it] + 4] = rB[it * 4 + 2];
                nB[b_base[it] + 6] = rB[it * 4 + 3];
            }
        }
        __syncthreads();
    }

    // ---- epilogue: BN + ReLU, stage through smem for coalesced stores ----
    const float inv = rsqrtf(1.0f + 1e-5f);
    float* Cs = smem;                          // reuse (all compute done)

#pragma unroll
    for (int i = 0; i < 4; ++i) {
        const int h0 = wm * 64 + i * 16 + gq;  // rows for c0,c1
        const int h1 = h0 + 8;                 // rows for c2,c3
        const float sc0 = gamma[rowStart + h0] * inv, bi0 = beta[rowStart + h0];
        const float sc1 = gamma[rowStart + h1] * inv, bi1 = beta[rowStart + h1];
#pragma unroll
        for (int j = 0; j < 4; ++j) {
            const int n0 = wn * 32 + j * 8 + 2 * tq;
            float v0 = fmaxf(fmaf(acc[i][j][0], sc0, bi0), 0.0f);
            float v1 = fmaxf(fmaf(acc[i][j][1], sc0, bi0), 0.0f);
            float v2 = fmaxf(fmaf(acc[i][j][2], sc1, bi1), 0.0f);
            float v3 = fmaxf(fmaf(acc[i][j][3], sc1, bi1), 0.0f);
            if (MODE == 0) { v0 = tf32r(v0); v1 = tf32r(v1); v2 = tf32r(v2); v3 = tf32r(v3); }
            if (MODE == 0) {
                // Cs[n][h]
                Cs[(n0 + 0) * CS_STRIDE + h0] = v0;
                Cs[(n0 + 1) * CS_STRIDE + h0] = v1;
                Cs[(n0 + 0) * CS_STRIDE + h1] = v2;
                Cs[(n0 + 1) * CS_STRIDE + h1] = v3;
            } else {
                // Cs[h][n]
                Cs[h0 * CS_STRIDE + n0 + 0] = v0;
                Cs[h0 * CS_STRIDE + n0 + 1] = v1;
                Cs[h1 * CS_STRIDE + n0 + 0] = v2;
                Cs[h1 * CS_STRIDE + n0 + 1] = v3;
            }
        }
    }
    __syncthreads();

#pragma unroll
    for (int it = 0; it < 16; ++it) {
        const int idx = tid + it * 256;        // 0..4095 float4s
        const int r = idx >> 5;                // staged row 0..127
        const int f = idx & 31;                // float4 within row
        const float4 v = *(const float4*)(Cs + r * CS_STRIDE + f * 4);
        if (MODE == 0) {
            // Y = g_y1 [B][N][HH]: row r = point, cols = channels
            *(float4*)(Y + ((size_t)b * NN + colStart + r) * HH + rowStart + f * 4) = v;
        } else {
            // Y = out [B][HH][NN]: row r = channel, cols = points
            *(float4*)(Y + ((size_t)b * HH + rowStart + r) * NN + colStart + f * 4) = v;
        }
    }
}

// ---------------------------------------------------------------------------
extern "C" void kernel_launch(void* const* d_in, const int* in_sizes, int n_in,
                              void* d_out, int out_size)
{
    const float* xyz1   = (const float*)d_in[0];
    const float* xyz2   = (const float*)d_in[1];
    const float* feat1  = (const float*)d_in[2];
    const float* feat2  = (const float*)d_in[3];
    const float* w1     = (const float*)d_in[4];
    const float* gamma1 = (const float*)d_in[5];
    const float* beta1  = (const float*)d_in[6];
    const float* w2     = (const float*)d_in[7];
    const float* gamma2 = (const float*)d_in[8];
    const float* beta2  = (const float*)d_in[9];
    float* out = (float*)d_out;

    cudaFuncSetAttribute(gemm_mma<CIN, 0>, cudaFuncAttributeMaxDynamicSharedMemorySize, DYN_BYTES);
    cudaFuncSetAttribute(gemm_mma<HH, 1>,  cudaFuncAttributeMaxDynamicSharedMemorySize, DYN_BYTES);

    // 1) 3-NN + weights
    nn_kernel<<<dim3(NN / 256, BB), 256>>>(xyz1, xyz2);
    // 2) feat2 -> point-major fp32
    f2t_kernel<<<dim3(MM / 32, C2 / 32, BB), dim3(32, 8)>>>(feat2);
    // 3) gather -> g_x channels [0,256)
    interp_x_kernel<<<dim3(NN / 8, BB), 256>>>();
    // 4) feat1 -> g_x channels [256,512)
    feat1_x_kernel<<<dim3(NN / 32, C1 / 32, BB), dim3(32, 8)>>>(feat1);
    // 5) layer 1: tf32 GEMM (K=512) + BN + ReLU -> g_y1 (point-major)
    gemm_mma<CIN, 0><<<dim3(NN / 128, HH / 128, BB), 256, DYN_BYTES>>>(w1, nullptr, gamma1, beta1);
    // 6) layer 2: tf32 GEMM (K=256) + BN + ReLU -> out (channel-major)
    gemm_mma<HH, 1><<<dim3(NN / 128, HH / 128, BB), 256, DYN_BYTES>>>(w2, out, gamma2, beta2);
}